// round 14
// baseline (speedup 1.0000x reference)
#include <cuda_runtime.h>

// Problem constants
#define TT   64
#define BB   1024
#define DZc  256
#define DXc  64
#define DHc  1024

#define ROWS 7                 // batch rows per CTA (7*146=1022, last CTA: 2)
#define NCTA 147               // one wave on 148 SMs
#define NTH  512               // 16 warps, 4/SMSP

// W1/Wx: k-pair interleave [kp][c][2]  (dense 16B/lane for 2-col threads)
// W2:    split-plane [kp][planeA: quads c0..c1][planeB: c2..c3] (dense for 4-col)
__device__ float g_W1p[DZc * DHc];   // 1 MB   (128 kp x 2048)
__device__ float g_Wxp[DXc * DHc];   // 256 KB (32 kp x 2048)
__device__ float g_W2p[DHc * DZc];   // 1 MB   (512 kp x 512)

// Dynamic shared memory layout (floats)
#define NZ   (ROWS * DZc)                      // 1792
#define NH   (ROWS * DHc)                      // 7168
#define OFF_Z    0
#define OFF_ZIN  (OFF_Z    + NZ)               // 1792
#define OFF_KSUM (OFF_ZIN  + NZ)               // 3584
#define OFF_XB   (OFF_KSUM + NZ)               // 5376
#define OFF_H    (OFF_XB   + NH)               // 12544
#define OFF_PART (OFF_H    + NH)               // 19712  [8][NZ] = 14336
#define OFF_XS   (OFF_PART + 8 * NZ)           // 34048  448
#define OFF_WT   (OFF_XS   + ROWS * DXc)       // 34496
#define OFF_B1   (OFF_WT   + DHc)              // 35520
#define OFF_B2   (OFF_B1   + DHc)              // 36544
#define SMEM_FLOATS (OFF_B2 + DZc)             // 36800 floats = 143.75 KB

typedef unsigned long long u64;

__device__ __forceinline__ void fma2(u64& acc, u64 a, u64 b)
{
    asm("fma.rn.f32x2 %0, %1, %2, %0;" : "+l"(acc) : "l"(a), "l"(b));
}
__device__ __forceinline__ float2 unpack2(u64 p)
{
    float2 v;
    asm("mov.b64 {%0, %1}, %2;" : "=f"(v.x), "=f"(v.y) : "l"(p));
    return v;
}
__device__ __forceinline__ float fast_tanh(float x)
{
    const float e = __expf(2.0f * x);
    return 1.0f - 2.0f * __fdividef(1.0f, 1.0f + e);
}

// ---------------------------------------------------------------------------
// Weight pack kernel: W1/Wx interleaved [kp][c][2]; W2 split-plane.
// ---------------------------------------------------------------------------
__global__ void pack_kernel(const float* __restrict__ W1,
                            const float* __restrict__ Wx,
                            const float* __restrict__ W2)
{
    const int i = blockIdx.x * blockDim.x + threadIdx.x;   // [0, 262144)
    {   // W1p: [kp][c][2], row = 2048 floats
        const int kp = i >> 11, rem = i & 2047;
        const int c = rem >> 1, par = rem & 1;
        g_W1p[i] = W1[(2 * kp + par) * DHc + c];
    }
    {   // W2p split-plane: WROW = 512, NC = 256
        const int kp = i >> 9, rem = i & 511;
        const int plane = rem >> 8, u = rem & 255;
        const int q = u >> 2, s = u & 3;
        const int col = q * 4 + plane * 2 + (s >> 1), par = s & 1;
        g_W2p[i] = W2[(2 * kp + par) * DZc + col];
    }
    if (i < DXc * DHc) {   // Wxp: [kp][c][2]
        const int kp = i >> 11, rem = i & 2047;
        const int c = rem >> 1, par = rem & 1;
        g_Wxp[i] = Wx[(2 * kp + par) * DHc + c];
    }
}

// ---------------------------------------------------------------------------
// 2-col full-K GEMM accumulate (GEMM1/xb): thread owns cols (c0,c0+1), 7 rows.
// Wcol = W*p + c0*2 (interleave layout): 16B load = both cols' kp pair, dense.
// ---------------------------------------------------------------------------
template <int KTOT, int INSTRIDE>
__device__ __forceinline__ void gemm_acc2(
    const float* in_s, const float* __restrict__ Wcol, u64* a0, u64* a1)
{
#pragma unroll
    for (int r = 0; r < ROWS; ++r) { a0[r] = 0ull; a1[r] = 0ull; }

#pragma unroll 4
    for (int k = 0; k < KTOT; k += 4) {
        const int kp = k >> 1;
        const ulonglong2 wA = *(const ulonglong2*)(Wcol + kp * (2 * DHc));        // kp:   (c0,c1)
        const ulonglong2 wB = *(const ulonglong2*)(Wcol + (kp + 1) * (2 * DHc));  // kp+1: (c0,c1)
#pragma unroll
        for (int r = 0; r < ROWS; ++r) {
            const ulonglong2 zp = *(const ulonglong2*)(in_s + r * INSTRIDE + k);  // broadcast
            fma2(a0[r], zp.x, wA.x);
            fma2(a1[r], zp.x, wA.y);
            fma2(a0[r], zp.y, wB.x);
            fma2(a1[r], zp.y, wB.y);
        }
    }
}

// ---------------------------------------------------------------------------
// Persistent kernel, 147 CTAs x 7 rows x 512 threads.
//   GEMM1: thread t -> cols [2t, 2t+2), full K=256, fused tanh.
//   GEMM2: kseg = t>>6 (8 segs of 128 k), cols [4(t&63), +4).
//   kseg g's h band [128g,128g+128) is written by threads [64g,64g+64) ==
//   the kseg-g threads themselves -> 64-thread named barrier g+1.
// ---------------------------------------------------------------------------
__global__ void __launch_bounds__(NTH, 1)
ode_kernel(const float* __restrict__ z0, const float* __restrict__ t,
           const float* __restrict__ x,  const float* __restrict__ wt,
           const float* __restrict__ b1, const float* __restrict__ b2,
           float* __restrict__ out)
{
    extern __shared__ float sm[];
    float* z_s    = sm + OFF_Z;      // [7][256]
    float* zin_s  = sm + OFF_ZIN;
    float* ksum_s = sm + OFF_KSUM;
    float* xb_s   = sm + OFF_XB;     // [7][1024]
    float* h_s    = sm + OFF_H;
    float* part_s = sm + OFF_PART;   // [8][7][256]
    float* xs_s   = sm + OFF_XS;     // [7][64]
    float* wt_s   = sm + OFF_WT;
    float* b1_s   = sm + OFF_B1;
    float* b2_s   = sm + OFF_B2;

    const int tid  = threadIdx.x;
    const int c0   = tid * 2;              // GEMM1 col pair
    const int kseg = tid >> 6;             // GEMM2 k segment 0..7
    const int j0   = (tid & 63) * 4;       // GEMM2 4-col block
    const int row0 = blockIdx.x * ROWS;

    const float* w1col = g_W1p + c0 * 2;                         // interleave
    const float* wxcol = g_Wxp + c0 * 2;
    const float* w2col = g_W2p + (tid & 63) * 4 + (kseg * 64) * 512;  // split-plane

    // RK4-combine mapping: thread owns col jj, rows rb.. (4 rows / 3 rows)
    const int jj = tid & 255;
    const int rb = (tid >> 8) * 4;         // 0 or 4
    const int nr = (tid >> 8) ? 3 : 4;

    // clamped global row per local row (last CTA: rows 5,6 -> 1023)
    int grow[ROWS];
#pragma unroll
    for (int r = 0; r < ROWS; ++r)
        grow[r] = (row0 + r < BB) ? (row0 + r) : (BB - 1);

    // cache small vectors; load z0
    wt_s[tid]       = wt[tid];
    wt_s[tid + NTH] = wt[tid + NTH];
    b1_s[tid]       = b1[tid];
    b1_s[tid + NTH] = b1[tid + NTH];
    if (tid < DZc) b2_s[tid] = b2[tid];
#pragma unroll
    for (int i = 0; i < 4; ++i) {
        const int p = i * NTH + tid;           // [0, 2048)
        if (p < NZ)
            z_s[p] = z0[grow[p >> 8] * DZc + (p & 255)];
    }
    __syncthreads();

    for (int step = 0; step < TT - 1; ++step) {
        const float t0 = __ldg(t + step);
        const float t1 = __ldg(t + step + 1);
        const float hstep = t1 - t0;
        const float tmid  = t0 + 0.5f * hstep;

        // stage x[step] rows [7][64]
        if (tid < ROWS * DXc) {
            const int r = tid >> 6, d = tid & 63;
            xs_s[tid] = x[(step * BB + grow[r]) * DXc + d];
        }
        __syncthreads();

        // ---- xb = x @ Wx + b1 (2-col, full K=64) ----
        {
            u64 a0[ROWS], a1[ROWS];
            gemm_acc2<DXc, DXc>(xs_s, wxcol, a0, a1);
            const float bb0 = b1_s[c0], bb1 = b1_s[c0 + 1];
#pragma unroll
            for (int r = 0; r < ROWS; ++r) {
                const float2 v0 = unpack2(a0[r]);
                const float2 v1 = unpack2(a1[r]);
                *(float2*)(xb_s + r * DHc + c0) =
                    make_float2(v0.x + v0.y + bb0, v1.x + v1.y + bb1);
            }
        }
        // no barrier: each thread reads back only its own xb columns

#pragma unroll 1
        for (int sub = 0; sub < 4; ++sub) {
            const float ts = (sub == 0) ? t0 : (sub == 3 ? t1 : tmid);
            const float* zi = (sub == 0) ? z_s : zin_s;

            // GEMM1 (2-col, full K=256) + fused tanh -> h_s
            {
                u64 a0[ROWS], a1[ROWS];
                gemm_acc2<DZc, DZc>(zi, w1col, a0, a1);
                const float w0 = wt_s[c0] * ts, w1 = wt_s[c0 + 1] * ts;
#pragma unroll
                for (int r = 0; r < ROWS; ++r) {
                    const float2 v0  = unpack2(a0[r]);
                    const float2 v1  = unpack2(a1[r]);
                    const float2 xbv = *(const float2*)(xb_s + r * DHc + c0);
                    *(float2*)(h_s + r * DHc + c0) =
                        make_float2(fast_tanh(v0.x + v0.y + xbv.x + w0),
                                    fast_tanh(v1.x + v1.y + xbv.y + w1));
                }
            }
            // kseg g's h band was written by these same 64 threads
            asm volatile("bar.sync %0, 64;" :: "r"(kseg + 1) : "memory");

            // GEMM2 (4-col, k band 128) -> partial[kseg]
            {
                u64 b0[ROWS], b1a[ROWS], b2a[ROWS], b3[ROWS];
#pragma unroll
                for (int r = 0; r < ROWS; ++r)
                    { b0[r] = 0ull; b1a[r] = 0ull; b2a[r] = 0ull; b3[r] = 0ull; }

                const float* hb = h_s + kseg * 128;
#pragma unroll 4
                for (int kk = 0; kk < 128; kk += 4) {
                    const int kp = kk >> 1;
                    const ulonglong2 wA = *(const ulonglong2*)(w2col + kp * 512);
                    const ulonglong2 wB = *(const ulonglong2*)(w2col + kp * 512 + 256);
                    const ulonglong2 wC = *(const ulonglong2*)(w2col + (kp + 1) * 512);
                    const ulonglong2 wD = *(const ulonglong2*)(w2col + (kp + 1) * 512 + 256);
#pragma unroll
                    for (int r = 0; r < ROWS; ++r) {
                        const ulonglong2 hp = *(const ulonglong2*)(hb + r * DHc + kk);
                        fma2(b0[r], hp.x, wA.x);
                        fma2(b1a[r], hp.x, wA.y);
                        fma2(b2a[r], hp.x, wB.x);
                        fma2(b3[r], hp.x, wB.y);
                        fma2(b0[r], hp.y, wC.x);
                        fma2(b1a[r], hp.y, wC.y);
                        fma2(b2a[r], hp.y, wD.x);
                        fma2(b3[r], hp.y, wD.y);
                    }
                }
#pragma unroll
                for (int r = 0; r < ROWS; ++r) {
                    const float2 v0 = unpack2(b0[r]);
                    const float2 v1 = unpack2(b1a[r]);
                    const float2 v2 = unpack2(b2a[r]);
                    const float2 v3 = unpack2(b3[r]);
                    *(float4*)(part_s + kseg * NZ + r * DZc + j0) =
                        make_float4(v0.x + v0.y, v1.x + v1.y,
                                    v2.x + v2.y, v3.x + v3.y);
                }
            }
            __syncthreads();

            // combine 8 partials + RK4 update: thread owns col jj, rows rb..rb+nr
            {
                const float bb = b2_s[jj];
#pragma unroll
                for (int r = 0; r < 4; ++r) {
                    if (r < nr) {
                        const int p = (rb + r) * DZc + jj;
                        float v = bb;
#pragma unroll
                        for (int s = 0; s < 8; ++s) v += part_s[s * NZ + p];
                        const float zv = z_s[p];
                        if (sub == 0) {
                            ksum_s[p] = v;
                            zin_s[p]  = zv + 0.5f * hstep * v;
                        } else if (sub == 1) {
                            ksum_s[p] += 2.f * v;
                            zin_s[p]  = zv + 0.5f * hstep * v;
                        } else if (sub == 2) {
                            ksum_s[p] += 2.f * v;
                            zin_s[p]  = zv + hstep * v;
                        } else {
                            z_s[p] = zv + (hstep * (1.f / 6.f)) * (ksum_s[p] + v);
                        }
                    }
                }
            }
            __syncthreads();
        }
    }

    // write z_final (skip clamped duplicate rows)
#pragma unroll
    for (int i = 0; i < 4; ++i) {
        const int p = i * NTH + tid;
        if (p < NZ && row0 + (p >> 8) < BB)
            out[(row0 + (p >> 8)) * DZc + (p & 255)] = z_s[p];
    }
}

extern "C" void kernel_launch(void* const* d_in, const int* in_sizes, int n_in,
                              void* d_out, int out_size)
{
    const float* z0 = (const float*)d_in[0];
    const float* t  = (const float*)d_in[1];
    const float* x  = (const float*)d_in[2];
    const float* W1 = (const float*)d_in[3];
    const float* Wx = (const float*)d_in[4];
    const float* wt = (const float*)d_in[5];
    const float* b1 = (const float*)d_in[6];
    const float* W2 = (const float*)d_in[7];
    const float* b2 = (const float*)d_in[8];
    float* out = (float*)d_out;

    pack_kernel<<<(DZc * DHc) / 256, 256>>>(W1, Wx, W2);

    const size_t smem = SMEM_FLOATS * sizeof(float);   // ~144 KB
    cudaFuncSetAttribute(ode_kernel,
                         cudaFuncAttributeMaxDynamicSharedMemorySize, (int)smem);
    ode_kernel<<<NCTA, NTH, smem>>>(z0, t, x, wt, b1, b2, out);
}

// round 16
// speedup vs baseline: 1.0697x; 1.0697x over previous
#include <cuda_runtime.h>

// Problem constants
#define TT   64
#define BB   1024
#define DZc  256
#define DXc  64
#define DHc  1024

#define ROWS 7                 // batch rows per CTA (7*146=1022, last CTA: 2)
#define NCTA 147               // one wave on 148 SMs
#define NTH  256

// Packed weight scratch, split-plane layout (unchanged from round 12/13):
//   row kp = [plane A: quads' cols 4q..4q+1][plane B: cols 4q+2..4q+3]
__device__ float g_W1p[DZc * DHc];   // 1 MB
__device__ float g_Wxp[DXc * DHc];   // 256 KB
__device__ float g_W2p[DHc * DZc];   // 1 MB

// Dynamic shared memory layout (floats)
#define NZ   (ROWS * DZc)                      // 1792
#define NH   (ROWS * DHc)                      // 7168
#define OFF_Z    0
#define OFF_ZIN  (OFF_Z    + NZ)
#define OFF_KSUM (OFF_ZIN  + NZ)
#define OFF_XB   (OFF_KSUM + NZ)
#define OFF_H    (OFF_XB   + NH)
#define OFF_PART (OFF_H    + NH)               // 4 * NZ
#define OFF_XS   (OFF_PART + 4 * NZ)           // ROWS*DXc = 448
#define OFF_WT   (OFF_XS   + ROWS * DXc)
#define OFF_B1   (OFF_WT   + DHc)
#define OFF_B2   (OFF_B1   + DHc)
#define SMEM_FLOATS (OFF_B2 + DZc)             // 29632 floats = 116 KB

typedef unsigned long long u64;

__device__ __forceinline__ void fma2(u64& acc, u64 a, u64 b)
{
    asm("fma.rn.f32x2 %0, %1, %2, %0;" : "+l"(acc) : "l"(a), "l"(b));
}
__device__ __forceinline__ float2 unpack2(u64 p)
{
    float2 v;
    asm("mov.b64 {%0, %1}, %2;" : "=f"(v.x), "=f"(v.y) : "l"(p));
    return v;
}
__device__ __forceinline__ float fast_tanh(float x)
{
    const float e = __expf(2.0f * x);
    return 1.0f - 2.0f * __fdividef(1.0f, 1.0f + e);
}

// ---------------------------------------------------------------------------
// Weight pack kernel: split-plane layout (identical to round 13)
// ---------------------------------------------------------------------------
__global__ void pack_kernel(const float* __restrict__ W1,
                            const float* __restrict__ Wx,
                            const float* __restrict__ W2)
{
    const int i = blockIdx.x * blockDim.x + threadIdx.x;   // [0, 262144)
    {   // W1p: WROW = 2048, NC = 1024
        const int kp = i >> 11, rem = i & 2047;
        const int plane = rem >> 10, u = rem & 1023;
        const int q = u >> 2, s = u & 3;
        const int col = q * 4 + plane * 2 + (s >> 1), par = s & 1;
        g_W1p[i] = W1[(2 * kp + par) * DHc + col];
    }
    {   // W2p: WROW = 512, NC = 256
        const int kp = i >> 9, rem = i & 511;
        const int plane = rem >> 8, u = rem & 255;
        const int q = u >> 2, s = u & 3;
        const int col = q * 4 + plane * 2 + (s >> 1), par = s & 1;
        g_W2p[i] = W2[(2 * kp + par) * DZc + col];
    }
    if (i < DXc * DHc) {   // Wxp
        const int kp = i >> 11, rem = i & 2047;
        const int plane = rem >> 10, u = rem & 1023;
        const int q = u >> 2, s = u & 3;
        const int col = q * 4 + plane * 2 + (s >> 1), par = s & 1;
        g_Wxp[i] = Wx[(2 * kp + par) * DHc + col];
    }
}

// ---------------------------------------------------------------------------
// k-packed 4-col GEMM accumulate: thread owns cols c0..c0+3, 7 rows, K=KTOT.
// unroll 8: 32 front-batched LDG.128 (~M_max cap) + full-window LDS hoisting;
// immediate-offset addressing keeps ALU flat (unlike manual prefetch).
// ---------------------------------------------------------------------------
template <int KTOT, int INSTRIDE, int WROW, int PLANE>
__device__ __forceinline__ void gemm_acc4(
    const float* in_s, const float* __restrict__ Wcol,
    u64* a0, u64* a1, u64* a2, u64* a3)
{
#pragma unroll
    for (int r = 0; r < ROWS; ++r) { a0[r] = 0ull; a1[r] = 0ull; a2[r] = 0ull; a3[r] = 0ull; }

#pragma unroll 8
    for (int k = 0; k < KTOT; k += 4) {
        const int kp = k >> 1;
        const ulonglong2 wA = *(const ulonglong2*)(Wcol + kp * WROW);
        const ulonglong2 wB = *(const ulonglong2*)(Wcol + kp * WROW + PLANE);
        const ulonglong2 wC = *(const ulonglong2*)(Wcol + (kp + 1) * WROW);
        const ulonglong2 wD = *(const ulonglong2*)(Wcol + (kp + 1) * WROW + PLANE);
#pragma unroll
        for (int r = 0; r < ROWS; ++r) {
            const ulonglong2 zp = *(const ulonglong2*)(in_s + r * INSTRIDE + k);  // broadcast
            fma2(a0[r], zp.x, wA.x);
            fma2(a1[r], zp.x, wA.y);
            fma2(a2[r], zp.x, wB.x);
            fma2(a3[r], zp.x, wB.y);
            fma2(a0[r], zp.y, wC.x);
            fma2(a1[r], zp.y, wC.y);
            fma2(a2[r], zp.y, wD.x);
            fma2(a3[r], zp.y, wD.y);
        }
    }
}

// ---------------------------------------------------------------------------
// Persistent kernel, 147 CTAs x 7 rows (structure identical to round 13).
// ---------------------------------------------------------------------------
__global__ void __launch_bounds__(NTH, 1)
ode_kernel(const float* __restrict__ z0, const float* __restrict__ t,
           const float* __restrict__ x,  const float* __restrict__ wt,
           const float* __restrict__ b1, const float* __restrict__ b2,
           float* __restrict__ out)
{
    extern __shared__ float sm[];
    float* z_s    = sm + OFF_Z;      // [7][256]
    float* zin_s  = sm + OFF_ZIN;
    float* ksum_s = sm + OFF_KSUM;
    float* xb_s   = sm + OFF_XB;     // [7][1024]
    float* h_s    = sm + OFF_H;
    float* part_s = sm + OFF_PART;   // [4][7][256]
    float* xs_s   = sm + OFF_XS;     // [7][64]
    float* wt_s   = sm + OFF_WT;
    float* b1_s   = sm + OFF_B1;
    float* b2_s   = sm + OFF_B2;

    const int tid  = threadIdx.x;
    const int c0   = tid * 4;              // GEMM1 4-col block
    const int kseg = tid >> 6;             // GEMM2 k segment 0..3
    const int j0   = (tid & 63) * 4;       // GEMM2 4-col block
    const int row0 = blockIdx.x * ROWS;

    const float* w1col = g_W1p + tid * 4;
    const float* wxcol = g_Wxp + tid * 4;
    const float* w2col = g_W2p + (tid & 63) * 4 + (kseg * 128) * 512;

    // clamped global row index per local row (last CTA: rows 5,6 -> 1023)
    int grow[ROWS];
#pragma unroll
    for (int r = 0; r < ROWS; ++r)
        grow[r] = (row0 + r < BB) ? (row0 + r) : (BB - 1);

    // cache small vectors; load z0 (NTH==DZc: i == local row)
#pragma unroll
    for (int i = 0; i < 4; ++i) {
        wt_s[i * NTH + tid] = wt[i * NTH + tid];
        b1_s[i * NTH + tid] = b1[i * NTH + tid];
    }
    b2_s[tid] = b2[tid];
#pragma unroll
    for (int i = 0; i < ROWS; ++i)
        z_s[i * DZc + tid] = z0[grow[i] * DZc + tid];
    __syncthreads();

    for (int step = 0; step < TT - 1; ++step) {
        const float t0 = __ldg(t + step);
        const float t1 = __ldg(t + step + 1);
        const float hstep = t1 - t0;
        const float tmid  = t0 + 0.5f * hstep;

        // stage x[step] rows [7][64]
#pragma unroll
        for (int i = 0; i < 2; ++i) {
            const int p = i * NTH + tid;           // [0, 512)
            const int r = p >> 6, d = p & 63;
            if (r < ROWS)
                xs_s[r * DXc + d] = x[(step * BB + grow[r]) * DXc + d];
        }
        __syncthreads();

        // ---- xb = x @ Wx + b1 ----
        {
            u64 a0[ROWS], a1[ROWS], a2[ROWS], a3[ROWS];
            gemm_acc4<DXc, DXc, 2 * DHc, DHc>(xs_s, wxcol, a0, a1, a2, a3);
            const float4 bb = *(const float4*)(b1_s + c0);
#pragma unroll
            for (int r = 0; r < ROWS; ++r) {
                const float2 v0 = unpack2(a0[r]);
                const float2 v1 = unpack2(a1[r]);
                const float2 v2 = unpack2(a2[r]);
                const float2 v3 = unpack2(a3[r]);
                *(float4*)(xb_s + r * DHc + c0) =
                    make_float4(v0.x + v0.y + bb.x, v1.x + v1.y + bb.y,
                                v2.x + v2.y + bb.z, v3.x + v3.y + bb.w);
            }
        }
        // no barrier: each thread reads back only its own xb columns

#pragma unroll 1
        for (int sub = 0; sub < 4; ++sub) {
            const float ts = (sub == 0) ? t0 : (sub == 3 ? t1 : tmid);
            const float* zi = (sub == 0) ? z_s : zin_s;

            // GEMM1 + fused tanh -> h_s
            {
                u64 a0[ROWS], a1[ROWS], a2[ROWS], a3[ROWS];
                gemm_acc4<DZc, DZc, 2 * DHc, DHc>(zi, w1col, a0, a1, a2, a3);
                const float4 wtv = *(const float4*)(wt_s + c0);
                const float w0 = wtv.x * ts, w1 = wtv.y * ts;
                const float w2 = wtv.z * ts, w3 = wtv.w * ts;
#pragma unroll
                for (int r = 0; r < ROWS; ++r) {
                    const float2 v0  = unpack2(a0[r]);
                    const float2 v1  = unpack2(a1[r]);
                    const float2 v2  = unpack2(a2[r]);
                    const float2 v3  = unpack2(a3[r]);
                    const float4 xbv = *(const float4*)(xb_s + r * DHc + c0);
                    *(float4*)(h_s + r * DHc + c0) =
                        make_float4(fast_tanh(v0.x + v0.y + xbv.x + w0),
                                    fast_tanh(v1.x + v1.y + xbv.y + w1),
                                    fast_tanh(v2.x + v2.y + xbv.z + w2),
                                    fast_tanh(v3.x + v3.y + xbv.w + w3));
                }
            }
            // kseg g reads h cols [256g,256g+256) written by these same 64 threads
            asm volatile("bar.sync %0, 64;" :: "r"(kseg + 1) : "memory");

            // GEMM2 (k band 256) -> partial
            {
                u64 a0[ROWS], a1[ROWS], a2[ROWS], a3[ROWS];
                gemm_acc4<256, DHc, 2 * DZc, DZc>(h_s + kseg * 256, w2col, a0, a1, a2, a3);
#pragma unroll
                for (int r = 0; r < ROWS; ++r) {
                    const float2 v0 = unpack2(a0[r]);
                    const float2 v1 = unpack2(a1[r]);
                    const float2 v2 = unpack2(a2[r]);
                    const float2 v3 = unpack2(a3[r]);
                    *(float4*)(part_s + kseg * NZ + r * DZc + j0) =
                        make_float4(v0.x + v0.y, v1.x + v1.y,
                                    v2.x + v2.y, v3.x + v3.y);
                }
            }
            __syncthreads();

            // combine 4 partials + RK4 update: thread owns col tid of all 7 rows
            {
                const float bb = b2_s[tid];
#pragma unroll
                for (int r = 0; r < ROWS; ++r) {
                    const int p = r * DZc + tid;
                    const float v = part_s[p] + part_s[NZ + p] +
                                    part_s[2 * NZ + p] + part_s[3 * NZ + p] + bb;
                    const float zv = z_s[p];
                    if (sub == 0) {
                        ksum_s[p] = v;
                        zin_s[p]  = zv + 0.5f * hstep * v;
                    } else if (sub == 1) {
                        ksum_s[p] += 2.f * v;
                        zin_s[p]  = zv + 0.5f * hstep * v;
                    } else if (sub == 2) {
                        ksum_s[p] += 2.f * v;
                        zin_s[p]  = zv + hstep * v;
                    } else {
                        z_s[p] = zv + (hstep * (1.f / 6.f)) * (ksum_s[p] + v);
                    }
                }
            }
            __syncthreads();
        }
    }

    // write z_final (skip clamped duplicate rows)
#pragma unroll
    for (int i = 0; i < ROWS; ++i)
        if (row0 + i < BB)
            out[(row0 + i) * DZc + tid] = z_s[i * DZc + tid];
}

extern "C" void kernel_launch(void* const* d_in, const int* in_sizes, int n_in,
                              void* d_out, int out_size)
{
    const float* z0 = (const float*)d_in[0];
    const float* t  = (const float*)d_in[1];
    const float* x  = (const float*)d_in[2];
    const float* W1 = (const float*)d_in[3];
    const float* Wx = (const float*)d_in[4];
    const float* wt = (const float*)d_in[5];
    const float* b1 = (const float*)d_in[6];
    const float* W2 = (const float*)d_in[7];
    const float* b2 = (const float*)d_in[8];
    float* out = (float*)d_out;

    pack_kernel<<<(DZc * DHc) / 256, 256>>>(W1, Wx, W2);

    const size_t smem = SMEM_FLOATS * sizeof(float);   // ~116 KB
    cudaFuncSetAttribute(ode_kernel,
                         cudaFuncAttributeMaxDynamicSharedMemorySize, (int)smem);
    ode_kernel<<<NCTA, NTH, smem>>>(z0, t, x, wt, b1, b2, out);
}